// round 12
// baseline (speedup 1.0000x reference)
#include <cuda_runtime.h>
#include <math.h>

// Problem shape (fixed by the dataset): f (4096,1024), noise (4096,1024), ref (4096,256)
#define BN 4096
#define LN 1024
#define DN 256
#define EPSV 1e-6f
#define NCT 128   // 8192 / 64 column tiles

// Scratch (no allocations allowed -> device globals)
__device__ float g_nf[BN];             // ||f_i||
__device__ float g_nn[BN];             // ||noise_i||
__device__ float g_nr[BN];             // ||ref_i||
__device__ float g_pos[BN];            // exp(cos(f_i, noise_i))
__device__ float g_partial[NCT * BN];  // [colTile][row] partial negative sums
__device__ float g_lpart[32];          // per-block loss partial sums

// ---------------------------------------------------------------------------
// Kernel 1: row norms of f, noise, ref
// ---------------------------------------------------------------------------
__global__ void norms_k(const float* __restrict__ f,
                        const float* __restrict__ nz,
                        const float* __restrict__ rf) {
    int i = blockIdx.x;
    int t = threadIdx.x;
    const float* fr = f  + (size_t)i * LN;
    const float* nr = nz + (size_t)i * LN;
    const float* rr = rf + (size_t)i * DN;
    float sf = 0.f, sn = 0.f, sr = 0.f;
    for (int k = t; k < LN; k += 128) { float a = fr[k]; sf += a * a;
                                        float b = nr[k]; sn += b * b; }
    for (int k = t; k < DN; k += 128) { float c = rr[k]; sr += c * c; }
    __shared__ float sh0[128], sh1[128], sh2[128];
    sh0[t] = sf; sh1[t] = sn; sh2[t] = sr;
    __syncthreads();
    for (int s = 64; s > 0; s >>= 1) {
        if (t < s) { sh0[t] += sh0[t + s]; sh1[t] += sh1[t + s]; sh2[t] += sh2[t + s]; }
        __syncthreads();
    }
    if (t == 0) {
        g_nf[i] = sqrtf(sh0[0]);
        g_nn[i] = sqrtf(sh1[0]);
        g_nr[i] = sqrtf(sh2[0]);
    }
}

// ---------------------------------------------------------------------------
// Kernel 2: fused tile kernel.
// Each block computes a 64x64 tile of the (B x 2B) matrix:
//   accF = f_i . cat_j   (K = 1024),  accR = ref_i . ref_{j mod B}  (K = 256)
// Epilogue: term = exp(cosF) * 0.5*(1 - cosR) * mask; row-reduce; write
// per-column-tile partials (deterministic, no atomics).
// ---------------------------------------------------------------------------
__global__ void __launch_bounds__(256)
main_k(const float* __restrict__ f,
       const float* __restrict__ nz,
       const float* __restrict__ rf) {
    // smem k-major tiles: [k][m] with +4 pad to keep 16B alignment & cut conflicts
    __shared__ float As[16][68];
    __shared__ float Bs[16][68];

    const int tid = threadIdx.x;
    const int tx = tid & 15;       // 16 column-groups
    const int ty = tid >> 4;       // 16 row-groups
    const int rowBase = blockIdx.y * 64;          // 0..4032
    const int colBase = blockIdx.x * 64;          // 0..8128
    const bool noiseSide = (colBase < BN);
    const int cbase2 = noiseSide ? colBase : (colBase - BN);   // j mod B base
    const float* csrc = noiseSide ? nz : f;

    // tile-load mapping: each thread loads one float4 per tile per k-chunk
    const int lrow = tid >> 2;            // 0..63
    const int lk4  = (tid & 3) << 2;      // 0,4,8,12

    float accF[4][4];
    float accR[4][4];
#pragma unroll
    for (int a = 0; a < 4; a++)
#pragma unroll
        for (int b = 0; b < 4; b++) { accF[a][b] = 0.f; accR[a][b] = 0.f; }

    // ---- GEMM 1: f (rows) x cat (cols), K = LN ----
    {
        const float* aptr = f    + (size_t)(rowBase + lrow) * LN + lk4;
        const float* bptr = csrc + (size_t)(cbase2 + lrow) * LN + lk4;
        for (int k0 = 0; k0 < LN; k0 += 16) {
            float4 av = *(const float4*)(aptr + k0);
            float4 bv = *(const float4*)(bptr + k0);
            __syncthreads();   // previous iteration's reads done
            As[lk4 + 0][lrow] = av.x; As[lk4 + 1][lrow] = av.y;
            As[lk4 + 2][lrow] = av.z; As[lk4 + 3][lrow] = av.w;
            Bs[lk4 + 0][lrow] = bv.x; Bs[lk4 + 1][lrow] = bv.y;
            Bs[lk4 + 2][lrow] = bv.z; Bs[lk4 + 3][lrow] = bv.w;
            __syncthreads();
#pragma unroll
            for (int kk = 0; kk < 16; kk++) {
                float4 a4 = *(const float4*)&As[kk][ty << 2];
                float4 b4 = *(const float4*)&Bs[kk][tx << 2];
                float am[4] = {a4.x, a4.y, a4.z, a4.w};
                float bn[4] = {b4.x, b4.y, b4.z, b4.w};
#pragma unroll
                for (int mi = 0; mi < 4; mi++)
#pragma unroll
                    for (int ni = 0; ni < 4; ni++)
                        accF[mi][ni] += am[mi] * bn[ni];
            }
        }
    }

    // ---- GEMM 2: ref (rows) x ref (j mod B cols), K = DN ----
    {
        const float* aptr = rf + (size_t)(rowBase + lrow) * DN + lk4;
        const float* bptr = rf + (size_t)(cbase2 + lrow) * DN + lk4;
        for (int k0 = 0; k0 < DN; k0 += 16) {
            float4 av = *(const float4*)(aptr + k0);
            float4 bv = *(const float4*)(bptr + k0);
            __syncthreads();
            As[lk4 + 0][lrow] = av.x; As[lk4 + 1][lrow] = av.y;
            As[lk4 + 2][lrow] = av.z; As[lk4 + 3][lrow] = av.w;
            Bs[lk4 + 0][lrow] = bv.x; Bs[lk4 + 1][lrow] = bv.y;
            Bs[lk4 + 2][lrow] = bv.z; Bs[lk4 + 3][lrow] = bv.w;
            __syncthreads();
#pragma unroll
            for (int kk = 0; kk < 16; kk++) {
                float4 a4 = *(const float4*)&As[kk][ty << 2];
                float4 b4 = *(const float4*)&Bs[kk][tx << 2];
                float am[4] = {a4.x, a4.y, a4.z, a4.w};
                float bn[4] = {b4.x, b4.y, b4.z, b4.w};
#pragma unroll
                for (int mi = 0; mi < 4; mi++)
#pragma unroll
                    for (int ni = 0; ni < 4; ni++)
                        accR[mi][ni] += am[mi] * bn[ni];
            }
        }
    }

    // ---- epilogue ----
    const int m0 = ty << 2;
    const int n0 = tx << 2;
    float ncj[4], nrj[4];
#pragma unroll
    for (int ni = 0; ni < 4; ni++) {
        int jm = cbase2 + n0 + ni;
        ncj[ni] = noiseSide ? g_nn[jm] : g_nf[jm];
        nrj[ni] = g_nr[jm];
    }
    float rowsum[4];
#pragma unroll
    for (int mi = 0; mi < 4; mi++) {
        const int i = rowBase + m0 + mi;
        const float nfi = g_nf[i];
        const float nri = g_nr[i];
        float s = 0.f;
#pragma unroll
        for (int ni = 0; ni < 4; ni++) {
            int j = colBase + n0 + ni;
            float cf = accF[mi][ni] / fmaxf(nfi * ncj[ni], EPSV);
            float mv = expf(cf);
            float w  = 0.5f * (1.0f - accR[mi][ni] / fmaxf(nri * nrj[ni], EPSV));
            float t  = mv * w;
            if (j == i) { g_pos[i] = mv; t = 0.f; }   // positive pair: record, exclude
            if (j == i + BN) t = 0.f;                 // self pair: exclude
            s += t;
        }
        rowsum[mi] = s;
    }

    // reduce across the 16 tx lanes sharing each row group (lanes 0-15 / 16-31)
#pragma unroll
    for (int mi = 0; mi < 4; mi++) {
#pragma unroll
        for (int off = 8; off > 0; off >>= 1)
            rowsum[mi] += __shfl_down_sync(0xffffffffu, rowsum[mi], off);
    }
    if (tx == 0) {
#pragma unroll
        for (int mi = 0; mi < 4; mi++)
            g_partial[(size_t)blockIdx.x * BN + rowBase + m0 + mi] = rowsum[mi];
    }
}

// ---------------------------------------------------------------------------
// Kernel 3: per-row negative sum + loss, block-level partial sums
// ---------------------------------------------------------------------------
__global__ void reduce_k() {
    int i = blockIdx.x * 128 + threadIdx.x;   // 32 blocks x 128 = 4096 rows
    float s = 0.f;
#pragma unroll 8
    for (int p = 0; p < NCT; p++)
        s += g_partial[(size_t)p * BN + i];
    float loss = -logf(g_pos[i] / (s + EPSV));
    __shared__ float sh[128];
    sh[threadIdx.x] = loss;
    __syncthreads();
    for (int st = 64; st > 0; st >>= 1) {
        if (threadIdx.x < st) sh[threadIdx.x] += sh[threadIdx.x + st];
        __syncthreads();
    }
    if (threadIdx.x == 0) g_lpart[blockIdx.x] = sh[0];
}

// ---------------------------------------------------------------------------
// Kernel 4: final mean
// ---------------------------------------------------------------------------
__global__ void final_k(float* __restrict__ out) {
    float v = g_lpart[threadIdx.x];   // 32 threads
#pragma unroll
    for (int off = 16; off > 0; off >>= 1)
        v += __shfl_down_sync(0xffffffffu, v, off);
    if (threadIdx.x == 0) out[0] = v / (float)BN;
}

// ---------------------------------------------------------------------------
extern "C" void kernel_launch(void* const* d_in, const int* in_sizes, int n_in,
                              void* d_out, int out_size) {
    const float* f  = (const float*)d_in[0];   // (4096, 1024)
    const float* nz = (const float*)d_in[1];   // (4096, 1024)
    const float* rf = (const float*)d_in[2];   // (4096, 256)
    float* out = (float*)d_out;

    norms_k<<<BN, 128>>>(f, nz, rf);
    dim3 grid(NCT, BN / 64);          // 128 x 64 tiles of the (4096 x 8192) matrix
    main_k<<<grid, 256>>>(f, nz, rf);
    reduce_k<<<32, 128>>>();
    final_k<<<1, 32>>>(out);
}

// round 14
// speedup vs baseline: 5.7525x; 5.7525x over previous
#include <cuda_runtime.h>
#include <cuda_bf16.h>
#include <math.h>
#include <stdint.h>

#define BN 4096
#define LN 1024
#define DN 256
#define EPSV 1e-6f
#define NCOLT 64      // 8192 / 128 column tiles

// ---------------- device scratch (no allocations allowed) ----------------
__device__ __align__(16) __nv_bfloat16 g_fb[BN * LN];
__device__ __align__(16) __nv_bfloat16 g_nb[BN * LN];
__device__ __align__(16) __nv_bfloat16 g_rb[BN * DN];
__device__ float g_nf[BN], g_nn[BN], g_nr[BN];
__device__ float g_pos[BN];
__device__ float g_partial[NCOLT * BN];
__device__ float g_lpart[32];

// ---------------- PTX helpers (all portable: sm_80+ non-suffixed) ----------
__device__ __forceinline__ uint32_t su32(const void* p) {
    uint32_t a;
    asm("{ .reg .u64 t; cvta.to.shared.u64 t, %1; cvt.u32.u64 %0, t; }" : "=r"(a) : "l"(p));
    return a;
}
__device__ __forceinline__ void ldsm4(uint32_t* r, uint32_t a) {
    asm volatile("ldmatrix.sync.aligned.m8n8.x4.shared.b16 {%0,%1,%2,%3}, [%4];"
        : "=r"(r[0]), "=r"(r[1]), "=r"(r[2]), "=r"(r[3]) : "r"(a));
}
__device__ __forceinline__ void mma16816(float* c, const uint32_t* a, const uint32_t* b) {
    asm volatile("mma.sync.aligned.m16n8k16.row.col.f32.bf16.bf16.f32 "
        "{%0,%1,%2,%3}, {%4,%5,%6,%7}, {%8,%9}, {%0,%1,%2,%3};"
        : "+f"(c[0]), "+f"(c[1]), "+f"(c[2]), "+f"(c[3])
        : "r"(a[0]), "r"(a[1]), "r"(a[2]), "r"(a[3]), "r"(b[0]), "r"(b[1]));
}
#define CP16(dst, src) \
    asm volatile("cp.async.cg.shared.global [%0], [%1], 16;" :: "r"(dst), "l"(src) : "memory")

// ---------------------------------------------------------------------------
// Kernel 0: fp32 -> bf16 conversion (vectorized)
// ---------------------------------------------------------------------------
__global__ void convert_k(const float4* __restrict__ f4,
                          const float4* __restrict__ n4,
                          const float4* __restrict__ r4) {
    int idx = blockIdx.x * 512 + threadIdx.x;   // 2048 x 512 = BN*LN/4
    float4 a = f4[idx];
    float4 b = n4[idx];
    __nv_bfloat162 alo = __floats2bfloat162_rn(a.x, a.y);
    __nv_bfloat162 ahi = __floats2bfloat162_rn(a.z, a.w);
    __nv_bfloat162 blo = __floats2bfloat162_rn(b.x, b.y);
    __nv_bfloat162 bhi = __floats2bfloat162_rn(b.z, b.w);
    uint2 ua, ub;
    ua.x = *(uint32_t*)&alo; ua.y = *(uint32_t*)&ahi;
    ub.x = *(uint32_t*)&blo; ub.y = *(uint32_t*)&bhi;
    ((uint2*)g_fb)[idx] = ua;
    ((uint2*)g_nb)[idx] = ub;
    if (idx < BN * DN / 4) {
        float4 c = r4[idx];
        __nv_bfloat162 clo = __floats2bfloat162_rn(c.x, c.y);
        __nv_bfloat162 chi = __floats2bfloat162_rn(c.z, c.w);
        uint2 uc; uc.x = *(uint32_t*)&clo; uc.y = *(uint32_t*)&chi;
        ((uint2*)g_rb)[idx] = uc;
    }
}

// ---------------------------------------------------------------------------
// Kernel 1: fp32 row norms from ORIGINAL data (matches reference denominator)
// ---------------------------------------------------------------------------
__global__ void norms_k(const float* __restrict__ f,
                        const float* __restrict__ nz,
                        const float* __restrict__ rf) {
    int i = blockIdx.x, t = threadIdx.x;
    const float* fr = f  + (size_t)i * LN;
    const float* nr = nz + (size_t)i * LN;
    const float* rr = rf + (size_t)i * DN;
    float sf = 0.f, sn = 0.f, sr = 0.f;
    for (int k = t; k < LN; k += 128) { float a = fr[k]; sf += a * a;
                                        float b = nr[k]; sn += b * b; }
    for (int k = t; k < DN; k += 128) { float c = rr[k]; sr += c * c; }
    __shared__ float sh0[128], sh1[128], sh2[128];
    sh0[t] = sf; sh1[t] = sn; sh2[t] = sr;
    __syncthreads();
    for (int s = 64; s > 0; s >>= 1) {
        if (t < s) { sh0[t] += sh0[t + s]; sh1[t] += sh1[t + s]; sh2[t] += sh2[t + s]; }
        __syncthreads();
    }
    if (t == 0) { g_nf[i] = sqrtf(sh0[0]); g_nn[i] = sqrtf(sh1[0]); g_nr[i] = sqrtf(sh2[0]); }
}

// ---------------------------------------------------------------------------
// Kernel 2: bf16 mma.sync dual-GEMM + fused epilogue. 128x128 tile per CTA,
// 8 warps of 64x32. cp.async double-buffered K=32 chunks, padded-40 smem rows
// (conflict-free ldmatrix). accF = f.cat (K=1024), accR = ref.ref (K=256).
// ---------------------------------------------------------------------------
__global__ void __launch_bounds__(256, 1)
main_k() {
    __shared__ __align__(16) __nv_bfloat16 sA[2][128 * 40];
    __shared__ __align__(16) __nv_bfloat16 sB[2][128 * 40];
    __shared__ float s_cn[128], s_cr[128], s_rf[128], s_rr[128];
    __shared__ float srow[128][4];

    const int tid = threadIdx.x;
    const int lane = tid & 31, wid = tid >> 5;
    const int wm = wid >> 2, wn = wid & 3;          // warp grid 2 x 4
    const int rowBase = blockIdx.y * 128;
    const int colBase = blockIdx.x * 128;
    const bool noiseSide = (colBase < BN);
    const int cb2 = noiseSide ? colBase : colBase - BN;

    const uint32_t aB0 = su32(sA[0]), aB1 = su32(sA[1]);
    const uint32_t bB0 = su32(sB[0]), bB1 = su32(sB[1]);

    // ldmatrix per-lane base offsets (bytes), padded row stride = 40 el = 80B
    // A 16x16 tile: row = wm*64 + (lane&15), colgroup = lane>>4
    const uint32_t aoff = (uint32_t)(((wm * 64 + (lane & 15)) * 40 + ((lane >> 4) << 3)) * 2);
    // B pair of n8k16 tiles: row n = wn*32 + (lane>>4)*8 + (lane&7), k-half = (lane>>3)&1
    const uint32_t boff = (uint32_t)(((wn * 32 + ((lane >> 4) << 3) + (lane & 7)) * 40
                                      + (((lane >> 3) & 1) << 3)) * 2);

    float accF[4][4][4], accR[4][4][4];
#pragma unroll
    for (int a = 0; a < 4; a++)
#pragma unroll
        for (int b = 0; b < 4; b++)
#pragma unroll
            for (int c = 0; c < 4; c++) { accF[a][b][c] = 0.f; accR[a][b][c] = 0.f; }

#define LOADSTEP(Ag, Bg, strideK, s, buf) do {                                  \
    uint32_t _ab = (buf) ? aB1 : aB0;                                           \
    uint32_t _bb = (buf) ? bB1 : bB0;                                           \
    _Pragma("unroll")                                                           \
    for (int ii = 0; ii < 2; ii++) {                                            \
        int idx = tid + ii * 256;                                               \
        int r = idx >> 2, c = idx & 3;                                          \
        uint32_t so = (uint32_t)((r * 40 + c * 8) * 2);                         \
        CP16(_ab + so, (Ag) + (size_t)r * (strideK) + (s) * 32 + c * 8);        \
        CP16(_bb + so, (Bg) + (size_t)r * (strideK) + (s) * 32 + c * 8);        \
    }                                                                           \
    asm volatile("cp.async.commit_group;" ::: "memory");                        \
} while (0)

#define COMPUTE(buf, acc) do {                                                  \
    uint32_t _ab = (buf) ? aB1 : aB0;                                           \
    uint32_t _bb = (buf) ? bB1 : bB0;                                           \
    _Pragma("unroll")                                                           \
    for (int kh = 0; kh < 2; kh++) {                                            \
        uint32_t af[4][4];                                                      \
        _Pragma("unroll")                                                       \
        for (int mt = 0; mt < 4; mt++)                                          \
            ldsm4(af[mt], _ab + aoff + (uint32_t)mt * 1280u + (uint32_t)kh * 32u); \
        uint32_t bf[2][4];                                                      \
        _Pragma("unroll")                                                       \
        for (int p = 0; p < 2; p++)                                             \
            ldsm4(bf[p], _bb + boff + (uint32_t)p * 1280u + (uint32_t)kh * 32u);\
        _Pragma("unroll")                                                       \
        for (int mt = 0; mt < 4; mt++)                                          \
            _Pragma("unroll")                                                   \
            for (int nt = 0; nt < 4; nt++)                                      \
                mma16816(acc[mt][nt], af[mt], &bf[nt >> 1][(nt & 1) * 2]);      \
    }                                                                           \
} while (0)

#define GEMM(Ag, Bg, strideK, NS, acc) do {                                     \
    LOADSTEP(Ag, Bg, strideK, 0, 0);                                            \
    for (int s = 0; s < (NS); s++) {                                            \
        int buf = s & 1;                                                        \
        if (s + 1 < (NS)) {                                                     \
            LOADSTEP(Ag, Bg, strideK, s + 1, buf ^ 1);                          \
            asm volatile("cp.async.wait_group 1;" ::: "memory");                \
        } else {                                                                \
            asm volatile("cp.async.wait_group 0;" ::: "memory");                \
        }                                                                       \
        __syncthreads();                                                        \
        COMPUTE(buf, acc);                                                      \
        __syncthreads();                                                        \
    }                                                                           \
} while (0)

    // GEMM 1: f (rows) x cat (cols), K = 1024
    {
        const __nv_bfloat16* A1 = g_fb + (size_t)rowBase * LN;
        const __nv_bfloat16* B1 = (noiseSide ? g_nb : g_fb) + (size_t)cb2 * LN;
        GEMM(A1, B1, LN, 32, accF);
    }
    // GEMM 2: ref (rows) x ref (cols mod B), K = 256
    {
        const __nv_bfloat16* A2 = g_rb + (size_t)rowBase * DN;
        const __nv_bfloat16* B2 = g_rb + (size_t)cb2 * DN;
        GEMM(A2, B2, DN, 8, accR);
    }

    // stage norms
    if (tid < 128) {
        s_rf[tid] = g_nf[rowBase + tid];
        s_rr[tid] = g_nr[rowBase + tid];
        int jm = cb2 + tid;
        s_cn[tid] = noiseSide ? g_nn[jm] : g_nf[jm];
        s_cr[tid] = g_nr[jm];
    }
    __syncthreads();

    // ---- fused epilogue on register fragments ----
#pragma unroll
    for (int mt = 0; mt < 4; mt++) {
#pragma unroll
        for (int h = 0; h < 2; h++) {
            int r = wm * 64 + mt * 16 + h * 8 + (lane >> 2);
            int i = rowBase + r;
            float nfi = s_rf[r], nri = s_rr[r];
            float rs = 0.f;
#pragma unroll
            for (int nt = 0; nt < 4; nt++) {
#pragma unroll
                for (int e = 0; e < 2; e++) {
                    int col = wn * 32 + nt * 8 + (lane & 3) * 2 + e;
                    int j = colBase + col;
                    float v1 = accF[mt][nt][h * 2 + e];
                    float v2 = accR[mt][nt][h * 2 + e];
                    float cf = __fdividef(v1, fmaxf(nfi * s_cn[col], EPSV));
                    float mv = __expf(cf);
                    float w  = 0.5f * (1.0f - __fdividef(v2, fmaxf(nri * s_cr[col], EPSV)));
                    float t = mv * w;
                    if (j == i) { g_pos[i] = mv; t = 0.f; }   // positive pair
                    if (j == i + BN) t = 0.f;                 // self pair
                    rs += t;
                }
            }
            rs += __shfl_xor_sync(0xffffffffu, rs, 1);
            rs += __shfl_xor_sync(0xffffffffu, rs, 2);
            if ((lane & 3) == 0) srow[r][wn] = rs;
        }
    }
    __syncthreads();
    if (tid < 128) {
        float s = srow[tid][0] + srow[tid][1] + srow[tid][2] + srow[tid][3];
        g_partial[(size_t)blockIdx.x * BN + rowBase + tid] = s;
    }
}

// ---------------------------------------------------------------------------
// Kernel 3: per-row negative sum + loss, block partials
// ---------------------------------------------------------------------------
__global__ void reduce_k() {
    int i = blockIdx.x * 128 + threadIdx.x;   // 32 x 128 = 4096 rows
    float s = 0.f;
#pragma unroll 8
    for (int p = 0; p < NCOLT; p++)
        s += g_partial[(size_t)p * BN + i];
    float loss = -logf(g_pos[i] / (s + EPSV));
    __shared__ float sh[128];
    sh[threadIdx.x] = loss;
    __syncthreads();
    for (int st = 64; st > 0; st >>= 1) {
        if (threadIdx.x < st) sh[threadIdx.x] += sh[threadIdx.x + st];
        __syncthreads();
    }
    if (threadIdx.x == 0) g_lpart[blockIdx.x] = sh[0];
}

// ---------------------------------------------------------------------------
// Kernel 4: final mean
// ---------------------------------------------------------------------------
__global__ void final_k(float* __restrict__ out) {
    float v = g_lpart[threadIdx.x];
#pragma unroll
    for (int off = 16; off > 0; off >>= 1)
        v += __shfl_down_sync(0xffffffffu, v, off);
    if (threadIdx.x == 0) out[0] = v / (float)BN;
}

// ---------------------------------------------------------------------------
extern "C" void kernel_launch(void* const* d_in, const int* in_sizes, int n_in,
                              void* d_out, int out_size) {
    (void)in_sizes; (void)n_in; (void)out_size;
    const float* f  = (const float*)d_in[0];   // (4096, 1024)
    const float* nz = (const float*)d_in[1];   // (4096, 1024)
    const float* rf = (const float*)d_in[2];   // (4096, 256)
    float* out = (float*)d_out;

    convert_k<<<2048, 512>>>((const float4*)f, (const float4*)nz, (const float4*)rf);
    norms_k<<<BN, 128>>>(f, nz, rf);
    dim3 grid(NCOLT, BN / 128);                // 64 x 32 tiles
    main_k<<<grid, 256>>>();
    reduce_k<<<32, 128>>>();
    final_k<<<1, 32>>>(out);
}

// round 15
// speedup vs baseline: 6.7978x; 1.1817x over previous
#include <cuda_runtime.h>
#include <cuda_bf16.h>
#include <math.h>
#include <stdint.h>

#define BN 4096
#define LN 1024
#define DN 256
#define EPSV 1e-6f
#define NCOLT 64      // 8192 / 128 column tiles

// per-stage smem tile: 128 rows x 40 bf16 (padded) = 10240 B
#define STAGE_BYTES 10240u
#define NSTAGE 4

// ---------------- device scratch (no allocations allowed) ----------------
__device__ __align__(16) __nv_bfloat16 g_fb[BN * LN];
__device__ __align__(16) __nv_bfloat16 g_nb[BN * LN];
__device__ __align__(16) __nv_bfloat16 g_rb[BN * DN];
__device__ float g_nf[BN], g_nn[BN], g_nr[BN];
__device__ float g_pos[BN];
__device__ float g_partial[NCOLT * BN];
__device__ float g_lpart[32];

// ---------------- PTX helpers (portable sm_80+, no arch suffix) ----------
__device__ __forceinline__ uint32_t su32(const void* p) {
    uint32_t a;
    asm("{ .reg .u64 t; cvta.to.shared.u64 t, %1; cvt.u32.u64 %0, t; }" : "=r"(a) : "l"(p));
    return a;
}
__device__ __forceinline__ void ldsm4(uint32_t* r, uint32_t a) {
    asm volatile("ldmatrix.sync.aligned.m8n8.x4.shared.b16 {%0,%1,%2,%3}, [%4];"
        : "=r"(r[0]), "=r"(r[1]), "=r"(r[2]), "=r"(r[3]) : "r"(a));
}
__device__ __forceinline__ void mma16816(float* c, const uint32_t* a, const uint32_t* b) {
    asm volatile("mma.sync.aligned.m16n8k16.row.col.f32.bf16.bf16.f32 "
        "{%0,%1,%2,%3}, {%4,%5,%6,%7}, {%8,%9}, {%0,%1,%2,%3};"
        : "+f"(c[0]), "+f"(c[1]), "+f"(c[2]), "+f"(c[3])
        : "r"(a[0]), "r"(a[1]), "r"(a[2]), "r"(a[3]), "r"(b[0]), "r"(b[1]));
}
#define CP16(dst, src) \
    asm volatile("cp.async.cg.shared.global [%0], [%1], 16;" :: "r"(dst), "l"(src) : "memory")
#define COMMIT() asm volatile("cp.async.commit_group;" ::: "memory")
#define WAIT2()  asm volatile("cp.async.wait_group 2;" ::: "memory")

// ---------------------------------------------------------------------------
// Kernel 0: fp32 -> bf16 conversion (vectorized)
// ---------------------------------------------------------------------------
__global__ void convert_k(const float4* __restrict__ f4,
                          const float4* __restrict__ n4,
                          const float4* __restrict__ r4) {
    int idx = blockIdx.x * 512 + threadIdx.x;   // 2048 x 512 = BN*LN/4
    float4 a = f4[idx];
    float4 b = n4[idx];
    __nv_bfloat162 alo = __floats2bfloat162_rn(a.x, a.y);
    __nv_bfloat162 ahi = __floats2bfloat162_rn(a.z, a.w);
    __nv_bfloat162 blo = __floats2bfloat162_rn(b.x, b.y);
    __nv_bfloat162 bhi = __floats2bfloat162_rn(b.z, b.w);
    uint2 ua, ub;
    ua.x = *(uint32_t*)&alo; ua.y = *(uint32_t*)&ahi;
    ub.x = *(uint32_t*)&blo; ub.y = *(uint32_t*)&bhi;
    ((uint2*)g_fb)[idx] = ua;
    ((uint2*)g_nb)[idx] = ub;
    if (idx < BN * DN / 4) {
        float4 c = r4[idx];
        __nv_bfloat162 clo = __floats2bfloat162_rn(c.x, c.y);
        __nv_bfloat162 chi = __floats2bfloat162_rn(c.z, c.w);
        uint2 uc; uc.x = *(uint32_t*)&clo; uc.y = *(uint32_t*)&chi;
        ((uint2*)g_rb)[idx] = uc;
    }
}

// ---------------------------------------------------------------------------
// Kernel 1: fp32 row norms from ORIGINAL data (matches reference denominator)
// ---------------------------------------------------------------------------
__global__ void norms_k(const float* __restrict__ f,
                        const float* __restrict__ nz,
                        const float* __restrict__ rf) {
    int i = blockIdx.x, t = threadIdx.x;
    const float* fr = f  + (size_t)i * LN;
    const float* nr = nz + (size_t)i * LN;
    const float* rr = rf + (size_t)i * DN;
    float sf = 0.f, sn = 0.f, sr = 0.f;
    for (int k = t; k < LN; k += 128) { float a = fr[k]; sf += a * a;
                                        float b = nr[k]; sn += b * b; }
    for (int k = t; k < DN; k += 128) { float c = rr[k]; sr += c * c; }
    __shared__ float sh0[128], sh1[128], sh2[128];
    sh0[t] = sf; sh1[t] = sn; sh2[t] = sr;
    __syncthreads();
    for (int s = 64; s > 0; s >>= 1) {
        if (t < s) { sh0[t] += sh0[t + s]; sh1[t] += sh1[t + s]; sh2[t] += sh2[t + s]; }
        __syncthreads();
    }
    if (t == 0) { g_nf[i] = sqrtf(sh0[0]); g_nn[i] = sqrtf(sh1[0]); g_nr[i] = sqrtf(sh2[0]); }
}

// ---------------------------------------------------------------------------
// Kernel 2: bf16 mma.sync dual-GEMM + fused epilogue. 128x128 tile per CTA,
// 8 warps of 64x32. 4-stage cp.async pipeline, ONE __syncthreads per chunk.
// ---------------------------------------------------------------------------
__global__ void __launch_bounds__(256, 1)
main_k() {
    extern __shared__ __align__(16) char dyn[];
    __shared__ float s_cn[128], s_cr[128], s_rf[128], s_rr[128];
    __shared__ float srow[128][4];

    const int tid = threadIdx.x;
    const int lane = tid & 31, wid = tid >> 5;
    const int wm = wid >> 2, wn = wid & 3;          // warp grid 2 x 4
    const int rowBase = blockIdx.y * 128;
    const int colBase = blockIdx.x * 128;
    const bool noiseSide = (colBase < BN);
    const int cb2 = noiseSide ? colBase : colBase - BN;

    const uint32_t aBase = su32(dyn);                       // 4 stages of A
    const uint32_t bBase = aBase + NSTAGE * STAGE_BYTES;    // 4 stages of B

    // ldmatrix per-lane base offsets (bytes), padded row stride = 40 el = 80B
    const uint32_t aoff = (uint32_t)(((wm * 64 + (lane & 15)) * 40 + ((lane >> 4) << 3)) * 2);
    const uint32_t boff = (uint32_t)(((wn * 32 + ((lane >> 4) << 3) + (lane & 7)) * 40
                                      + (((lane >> 3) & 1) << 3)) * 2);

    float accF[4][4][4], accR[4][4][4];
#pragma unroll
    for (int a = 0; a < 4; a++)
#pragma unroll
        for (int b = 0; b < 4; b++)
#pragma unroll
            for (int c = 0; c < 4; c++) { accF[a][b][c] = 0.f; accR[a][b][c] = 0.f; }

    // per-thread load mapping: 2 x (row, 16B) per tile per chunk
    const int lr0 = tid >> 2,        lc0 = (tid & 3) * 8;
    const int lr1 = (tid + 256) >> 2, lc1 = lc0;

#define LOADSTEP(Ag, Bg, strideK, s, st) do {                                   \
    uint32_t _ab = aBase + (uint32_t)(st) * STAGE_BYTES;                        \
    uint32_t _bb = bBase + (uint32_t)(st) * STAGE_BYTES;                        \
    uint32_t so0 = (uint32_t)((lr0 * 40 + lc0) * 2);                            \
    uint32_t so1 = (uint32_t)((lr1 * 40 + lc1) * 2);                            \
    CP16(_ab + so0, (Ag) + (size_t)lr0 * (strideK) + (s) * 32 + lc0);           \
    CP16(_bb + so0, (Bg) + (size_t)lr0 * (strideK) + (s) * 32 + lc0);           \
    CP16(_ab + so1, (Ag) + (size_t)lr1 * (strideK) + (s) * 32 + lc1);           \
    CP16(_bb + so1, (Bg) + (size_t)lr1 * (strideK) + (s) * 32 + lc1);           \
    COMMIT();                                                                   \
} while (0)

#define COMPUTE(st, acc) do {                                                   \
    uint32_t _ab = aBase + (uint32_t)(st) * STAGE_BYTES;                        \
    uint32_t _bb = bBase + (uint32_t)(st) * STAGE_BYTES;                        \
    _Pragma("unroll")                                                           \
    for (int kh = 0; kh < 2; kh++) {                                            \
        uint32_t af[4][4];                                                      \
        _Pragma("unroll")                                                       \
        for (int mt = 0; mt < 4; mt++)                                          \
            ldsm4(af[mt], _ab + aoff + (uint32_t)mt * 1280u + (uint32_t)kh * 32u); \
        uint32_t bf[2][4];                                                      \
        _Pragma("unroll")                                                       \
        for (int p = 0; p < 2; p++)                                             \
            ldsm4(bf[p], _bb + boff + (uint32_t)p * 1280u + (uint32_t)kh * 32u);\
        _Pragma("unroll")                                                       \
        for (int mt = 0; mt < 4; mt++)                                          \
            _Pragma("unroll")                                                   \
            for (int nt = 0; nt < 4; nt++)                                      \
                mma16816(acc[mt][nt], af[mt], &bf[nt >> 1][(nt & 1) * 2]);      \
    }                                                                           \
} while (0)

    // 4-stage pipeline, one sync per chunk:
    //   prologue: commit chunks 0..2 (empty groups if past NS)
    //   iter s:   wait_group 2 (chunk s resident) -> sync -> compute buf s%4
    //             -> load chunk s+3 into buf (s+3)%4 (== (s-1)%4, safe post-sync)
#define GEMM(Ag, Bg, strideK, NS, acc) do {                                     \
    _Pragma("unroll")                                                           \
    for (int p = 0; p < 3; p++) {                                               \
        if (p < (NS)) LOADSTEP(Ag, Bg, strideK, p, p);                          \
        else COMMIT();                                                          \
    }                                                                           \
    for (int s = 0; s < (NS); s++) {                                            \
        WAIT2();                                                                \
        __syncthreads();                                                        \
        COMPUTE(s & 3, acc);                                                    \
        if (s + 3 < (NS)) LOADSTEP(Ag, Bg, strideK, s + 3, (s + 3) & 3);        \
        else COMMIT();                                                          \
    }                                                                           \
} while (0)

    // GEMM 1: f (rows) x cat (cols), K = 1024
    {
        const __nv_bfloat16* A1 = g_fb + (size_t)rowBase * LN;
        const __nv_bfloat16* B1 = (noiseSide ? g_nb : g_fb) + (size_t)cb2 * LN;
        GEMM(A1, B1, LN, 32, accF);
    }
    // GEMM 2: ref (rows) x ref (cols mod B), K = 256
    {
        const __nv_bfloat16* A2 = g_rb + (size_t)rowBase * DN;
        const __nv_bfloat16* B2 = g_rb + (size_t)cb2 * DN;
        GEMM(A2, B2, DN, 8, accR);
    }
    asm volatile("cp.async.wait_group 0;" ::: "memory");

    // stage norms
    if (tid < 128) {
        s_rf[tid] = g_nf[rowBase + tid];
        s_rr[tid] = g_nr[rowBase + tid];
        int jm = cb2 + tid;
        s_cn[tid] = noiseSide ? g_nn[jm] : g_nf[jm];
        s_cr[tid] = g_nr[jm];
    }
    __syncthreads();

    // ---- fused epilogue on register fragments ----
#pragma unroll
    for (int mt = 0; mt < 4; mt++) {
#pragma unroll
        for (int h = 0; h < 2; h++) {
            int r = wm * 64 + mt * 16 + h * 8 + (lane >> 2);
            int i = rowBase + r;
            float nfi = s_rf[r], nri = s_rr[r];
            float rs = 0.f;
#pragma unroll
            for (int nt = 0; nt < 4; nt++) {
#pragma unroll
                for (int e = 0; e < 2; e++) {
                    int col = wn * 32 + nt * 8 + (lane & 3) * 2 + e;
                    int j = colBase + col;
                    float v1 = accF[mt][nt][h * 2 + e];
                    float v2 = accR[mt][nt][h * 2 + e];
                    float cf = __fdividef(v1, fmaxf(nfi * s_cn[col], EPSV));
                    float mv = __expf(cf);
                    float w  = 0.5f * (1.0f - __fdividef(v2, fmaxf(nri * s_cr[col], EPSV)));
                    float t = mv * w;
                    if (j == i) { g_pos[i] = mv; t = 0.f; }   // positive pair
                    if (j == i + BN) t = 0.f;                 // self pair
                    rs += t;
                }
            }
            rs += __shfl_xor_sync(0xffffffffu, rs, 1);
            rs += __shfl_xor_sync(0xffffffffu, rs, 2);
            if ((lane & 3) == 0) srow[r][wn] = rs;
        }
    }
    __syncthreads();
    if (tid < 128) {
        float s = srow[tid][0] + srow[tid][1] + srow[tid][2] + srow[tid][3];
        g_partial[(size_t)blockIdx.x * BN + rowBase + tid] = s;
    }
}

// ---------------------------------------------------------------------------
// Kernel 3: per-row negative sum + loss, block partials
// ---------------------------------------------------------------------------
__global__ void reduce_k() {
    int i = blockIdx.x * 128 + threadIdx.x;   // 32 x 128 = 4096 rows
    float s = 0.f;
#pragma unroll 8
    for (int p = 0; p < NCOLT; p++)
        s += g_partial[(size_t)p * BN + i];
    float loss = -logf(g_pos[i] / (s + EPSV));
    __shared__ float sh[128];
    sh[threadIdx.x] = loss;
    __syncthreads();
    for (int st = 64; st > 0; st >>= 1) {
        if (threadIdx.x < st) sh[threadIdx.x] += sh[threadIdx.x + st];
        __syncthreads();
    }
    if (threadIdx.x == 0) g_lpart[blockIdx.x] = sh[0];
}

// ---------------------------------------------------------------------------
// Kernel 4: final mean
// ---------------------------------------------------------------------------
__global__ void final_k(float* __restrict__ out) {
    float v = g_lpart[threadIdx.x];
#pragma unroll
    for (int off = 16; off > 0; off >>= 1)
        v += __shfl_down_sync(0xffffffffu, v, off);
    if (threadIdx.x == 0) out[0] = v / (float)BN;
}

// ---------------------------------------------------------------------------
extern "C" void kernel_launch(void* const* d_in, const int* in_sizes, int n_in,
                              void* d_out, int out_size) {
    (void)in_sizes; (void)n_in; (void)out_size;
    const float* f  = (const float*)d_in[0];   // (4096, 1024)
    const float* nz = (const float*)d_in[1];   // (4096, 1024)
    const float* rf = (const float*)d_in[2];   // (4096, 256)
    float* out = (float*)d_out;

    const int DSMEM = 2 * NSTAGE * STAGE_BYTES;   // 81920 B
    cudaFuncSetAttribute(main_k, cudaFuncAttributeMaxDynamicSharedMemorySize, DSMEM);

    convert_k<<<2048, 512>>>((const float4*)f, (const float4*)nz, (const float4*)rf);
    norms_k<<<BN, 128>>>(f, nz, rf);
    dim3 grid(NCOLT, BN / 128);                // 64 x 32 tiles
    main_k<<<grid, 256, DSMEM>>>();
    reduce_k<<<32, 128>>>();
    final_k<<<1, 32>>>(out);
}

// round 16
// speedup vs baseline: 8.6191x; 1.2679x over previous
#include <cuda_runtime.h>
#include <cuda_bf16.h>
#include <math.h>
#include <stdint.h>

#define BN 4096
#define LN 1024
#define DN 256
#define EPSV 1e-6f
#define NCOLT 64      // 64 partial slots (32 left + 32 right)

// per-stage smem tile: 128 rows x 72 bf16 (64 + 8 pad) = 18432 B
#define STAGE_BYTES 18432u
#define NSTAGE 4

// ---------------- device scratch (no allocations allowed) ----------------
__device__ __align__(16) __nv_bfloat16 g_fb[BN * LN];
__device__ __align__(16) __nv_bfloat16 g_nb[BN * LN];
__device__ __align__(16) __nv_bfloat16 g_rb[BN * DN];
__device__ float g_nf[BN], g_nn[BN], g_nr[BN];
__device__ float g_pos[BN];
__device__ float g_partial[NCOLT * BN];
__device__ float g_lpart[32];

// ---------------- PTX helpers (portable sm_80+, no arch suffix) ----------
__device__ __forceinline__ uint32_t su32(const void* p) {
    uint32_t a;
    asm("{ .reg .u64 t; cvta.to.shared.u64 t, %1; cvt.u32.u64 %0, t; }" : "=r"(a) : "l"(p));
    return a;
}
__device__ __forceinline__ void ldsm4(uint32_t* r, uint32_t a) {
    asm volatile("ldmatrix.sync.aligned.m8n8.x4.shared.b16 {%0,%1,%2,%3}, [%4];"
        : "=r"(r[0]), "=r"(r[1]), "=r"(r[2]), "=r"(r[3]) : "r"(a));
}
__device__ __forceinline__ void mma16816(float* c, const uint32_t* a, const uint32_t* b) {
    asm volatile("mma.sync.aligned.m16n8k16.row.col.f32.bf16.bf16.f32 "
        "{%0,%1,%2,%3}, {%4,%5,%6,%7}, {%8,%9}, {%0,%1,%2,%3};"
        : "+f"(c[0]), "+f"(c[1]), "+f"(c[2]), "+f"(c[3])
        : "r"(a[0]), "r"(a[1]), "r"(a[2]), "r"(a[3]), "r"(b[0]), "r"(b[1]));
}
#define CP16(dst, src) \
    asm volatile("cp.async.cg.shared.global [%0], [%1], 16;" :: "r"(dst), "l"(src) : "memory")
#define COMMIT() asm volatile("cp.async.commit_group;" ::: "memory")
#define WAIT2()  asm volatile("cp.async.wait_group 2;" ::: "memory")

// ---------------------------------------------------------------------------
// Kernel 0: fused bf16 convert + fp32 row norms (one read pass). Block = row.
// ---------------------------------------------------------------------------
__global__ void __launch_bounds__(256)
prep_k(const float4* __restrict__ f4,
       const float4* __restrict__ n4,
       const float4* __restrict__ r4) {
    int i = blockIdx.x, t = threadIdx.x;
    int idx = i * 256 + t;                      // float4 index into f / noise
    float4 a = f4[idx];
    float4 b = n4[idx];
    __nv_bfloat162 alo = __floats2bfloat162_rn(a.x, a.y);
    __nv_bfloat162 ahi = __floats2bfloat162_rn(a.z, a.w);
    __nv_bfloat162 blo = __floats2bfloat162_rn(b.x, b.y);
    __nv_bfloat162 bhi = __floats2bfloat162_rn(b.z, b.w);
    uint2 ua, ub;
    ua.x = *(uint32_t*)&alo; ua.y = *(uint32_t*)&ahi;
    ub.x = *(uint32_t*)&blo; ub.y = *(uint32_t*)&bhi;
    ((uint2*)g_fb)[idx] = ua;
    ((uint2*)g_nb)[idx] = ub;
    float sf = a.x * a.x + a.y * a.y + a.z * a.z + a.w * a.w;
    float sn = b.x * b.x + b.y * b.y + b.z * b.z + b.w * b.w;
    float sr = 0.f;
    if (t < 64) {
        int ridx = i * 64 + t;
        float4 c = r4[ridx];
        __nv_bfloat162 clo = __floats2bfloat162_rn(c.x, c.y);
        __nv_bfloat162 chi = __floats2bfloat162_rn(c.z, c.w);
        uint2 uc; uc.x = *(uint32_t*)&clo; uc.y = *(uint32_t*)&chi;
        ((uint2*)g_rb)[ridx] = uc;
        sr = c.x * c.x + c.y * c.y + c.z * c.z + c.w * c.w;
    }
    __shared__ float sh0[256], sh1[256], sh2[256];
    sh0[t] = sf; sh1[t] = sn; sh2[t] = sr;
    __syncthreads();
    for (int s = 128; s > 0; s >>= 1) {
        if (t < s) { sh0[t] += sh0[t + s]; sh1[t] += sh1[t + s]; sh2[t] += sh2[t + s]; }
        __syncthreads();
    }
    if (t == 0) { g_nf[i] = sqrtf(sh0[0]); g_nn[i] = sqrtf(sh1[0]); g_nr[i] = sqrtf(sh2[0]); }
}

// ---------------------------------------------------------------------------
// Kernel 2: bf16 mma.sync dual-GEMM + fused epilogue, 128x128 tiles.
// Right half (f.f^T) is symmetric: only upper-triangle tiles computed; their
// column sums provide the transposed tiles' row sums.
// ---------------------------------------------------------------------------
__global__ void __launch_bounds__(256, 1)
main_k() {
    const int bi = blockIdx.y;            // row block
    const int bx = blockIdx.x;            // 0..31 left (noise), 32..63 right (f)
    const bool right = (bx >= 32);
    const int bj = right ? bx - 32 : bx;  // col block mod 32
    if (right && bi > bj) return;         // lower triangle of right half: skip
    const bool sym = right && (bi < bj);  // off-diagonal: also emit colsums

    extern __shared__ __align__(16) char dyn[];
    __shared__ float s_cn[128], s_cr[128], s_rf[128], s_rr[128];
    __shared__ float srow[128][4];
    __shared__ float scs[128][2];

    const int tid = threadIdx.x;
    const int lane = tid & 31, wid = tid >> 5;
    const int wm = wid >> 2, wn = wid & 3;          // warp grid 2 x 4
    const int rowBase = bi * 128;
    const int colBase = bx * 128;                   // global col (0..8191)
    const int cb2 = bj * 128;                       // col mod B

    const uint32_t aBase = su32(dyn);
    const uint32_t bBase = aBase + NSTAGE * STAGE_BYTES;

    // ldmatrix per-lane base offsets (bytes), padded row stride = 72 el = 144B
    const uint32_t aoff = (uint32_t)(((wm * 64 + (lane & 15)) * 72 + ((lane >> 4) << 3)) * 2);
    const uint32_t boff = (uint32_t)(((wn * 32 + ((lane >> 4) << 3) + (lane & 7)) * 72
                                      + (((lane >> 3) & 1) << 3)) * 2);

    float accF[4][4][4], accR[4][4][4];
#pragma unroll
    for (int a = 0; a < 4; a++)
#pragma unroll
        for (int b = 0; b < 4; b++)
#pragma unroll
            for (int c = 0; c < 4; c++) { accF[a][b][c] = 0.f; accR[a][b][c] = 0.f; }

#define LOADSTEP(Ag, Bg, strideK, s, st) do {                                   \
    uint32_t _ab = aBase + (uint32_t)(st) * STAGE_BYTES;                        \
    uint32_t _bb = bBase + (uint32_t)(st) * STAGE_BYTES;                        \
    _Pragma("unroll")                                                           \
    for (int ii = 0; ii < 4; ii++) {                                            \
        int idx = tid + ii * 256;                                               \
        int r = idx >> 3, c = (idx & 7) * 8;                                    \
        uint32_t so = (uint32_t)((r * 72 + c) * 2);                             \
        CP16(_ab + so, (Ag) + (size_t)r * (strideK) + (s) * 64 + c);            \
        CP16(_bb + so, (Bg) + (size_t)r * (strideK) + (s) * 64 + c);            \
    }                                                                           \
    COMMIT();                                                                   \
} while (0)

#define COMPUTE(st, acc) do {                                                   \
    uint32_t _ab = aBase + (uint32_t)(st) * STAGE_BYTES;                        \
    uint32_t _bb = bBase + (uint32_t)(st) * STAGE_BYTES;                        \
    _Pragma("unroll")                                                           \
    for (int kh = 0; kh < 4; kh++) {                                            \
        uint32_t af[4][4];                                                      \
        _Pragma("unroll")                                                       \
        for (int mt = 0; mt < 4; mt++)                                          \
            ldsm4(af[mt], _ab + aoff + (uint32_t)mt * 2304u + (uint32_t)kh * 32u); \
        uint32_t bf[2][4];                                                      \
        _Pragma("unroll")                                                       \
        for (int p = 0; p < 2; p++)                                             \
            ldsm4(bf[p], _bb + boff + (uint32_t)p * 2304u + (uint32_t)kh * 32u);\
        _Pragma("unroll")                                                       \
        for (int mt = 0; mt < 4; mt++)                                          \
            _Pragma("unroll")                                                   \
            for (int nt = 0; nt < 4; nt++)                                      \
                mma16816(acc[mt][nt], af[mt], &bf[nt >> 1][(nt & 1) * 2]);      \
    }                                                                           \
} while (0)

    // 4-stage pipeline, one __syncthreads per chunk
#define GEMM(Ag, Bg, strideK, NS, acc) do {                                     \
    _Pragma("unroll")                                                           \
    for (int p = 0; p < 3; p++) {                                               \
        if (p < (NS)) LOADSTEP(Ag, Bg, strideK, p, p);                          \
        else COMMIT();                                                          \
    }                                                                           \
    for (int s = 0; s < (NS); s++) {                                            \
        WAIT2();                                                                \
        __syncthreads();                                                        \
        COMPUTE(s & 3, acc);                                                    \
        if (s + 3 < (NS)) LOADSTEP(Ag, Bg, strideK, s + 3, (s + 3) & 3);        \
        else COMMIT();                                                          \
    }                                                                           \
} while (0)

    // GEMM 1: f (rows) x cat (cols), K = 1024, 16 chunks of 64
    {
        const __nv_bfloat16* A1 = g_fb + (size_t)rowBase * LN;
        const __nv_bfloat16* B1 = (right ? g_fb : g_nb) + (size_t)cb2 * LN;
        GEMM(A1, B1, LN, 16, accF);
    }
    // GEMM 2: ref (rows) x ref (cols mod B), K = 256, 4 chunks of 64
    {
        const __nv_bfloat16* A2 = g_rb + (size_t)rowBase * DN;
        const __nv_bfloat16* B2 = g_rb + (size_t)cb2 * DN;
        GEMM(A2, B2, DN, 4, accR);
    }
    asm volatile("cp.async.wait_group 0;" ::: "memory");

    // stage norms
    if (tid < 128) {
        s_rf[tid] = g_nf[rowBase + tid];
        s_rr[tid] = g_nr[rowBase + tid];
        int jm = cb2 + tid;
        s_cn[tid] = right ? g_nf[jm] : g_nn[jm];
        s_cr[tid] = g_nr[jm];
    }
    __syncthreads();

    // ---- fused epilogue ----
    float cs[8];
#pragma unroll
    for (int k = 0; k < 8; k++) cs[k] = 0.f;

#pragma unroll
    for (int mt = 0; mt < 4; mt++) {
#pragma unroll
        for (int h = 0; h < 2; h++) {
            int r = wm * 64 + mt * 16 + h * 8 + (lane >> 2);
            int i = rowBase + r;
            float nfi = s_rf[r], nri = s_rr[r];
            float rs = 0.f;
#pragma unroll
            for (int nt = 0; nt < 4; nt++) {
#pragma unroll
                for (int e = 0; e < 2; e++) {
                    int col = wn * 32 + nt * 8 + (lane & 3) * 2 + e;
                    int j = colBase + col;
                    float v1 = accF[mt][nt][h * 2 + e];
                    float v2 = accR[mt][nt][h * 2 + e];
                    float cf = __fdividef(v1, fmaxf(nfi * s_cn[col], EPSV));
                    float mv = __expf(cf);
                    float w  = 0.5f * (1.0f - __fdividef(v2, fmaxf(nri * s_cr[col], EPSV)));
                    float t = mv * w;
                    if (j == i) { g_pos[i] = mv; t = 0.f; }   // positive pair (left diag)
                    if (j == i + BN) t = 0.f;                 // self pair (right diag)
                    rs += t;
                    cs[nt * 2 + e] += t;                      // colsum (used iff sym)
                }
            }
            rs += __shfl_xor_sync(0xffffffffu, rs, 1);
            rs += __shfl_xor_sync(0xffffffffu, rs, 2);
            if ((lane & 3) == 0) srow[r][wn] = rs;
        }
    }
    if (sym) {
        // reduce colsums over the 8 row-lanes (lane bits 2..4), all rows of wm-half
#pragma unroll
        for (int k = 0; k < 8; k++) {
            cs[k] += __shfl_xor_sync(0xffffffffu, cs[k], 4);
            cs[k] += __shfl_xor_sync(0xffffffffu, cs[k], 8);
            cs[k] += __shfl_xor_sync(0xffffffffu, cs[k], 16);
        }
        if ((lane >> 2) == 0) {
#pragma unroll
            for (int nt = 0; nt < 4; nt++)
#pragma unroll
                for (int e = 0; e < 2; e++) {
                    int col = wn * 32 + nt * 8 + (lane & 3) * 2 + e;
                    scs[col][wm] = cs[nt * 2 + e];
                }
        }
    }
    __syncthreads();
    if (tid < 128) {
        float s = srow[tid][0] + srow[tid][1] + srow[tid][2] + srow[tid][3];
        g_partial[(size_t)bx * BN + rowBase + tid] = s;   // rowsum -> slot bx, block bi
        if (sym) {
            // transposed tile's rowsum = this tile's colsum -> slot 32+bi, block bj
            g_partial[(size_t)(32 + bi) * BN + (size_t)cb2 + tid] = scs[tid][0] + scs[tid][1];
        }
    }
}

// ---------------------------------------------------------------------------
// Kernel 3: per-row negative sum + loss, block partials
// ---------------------------------------------------------------------------
__global__ void reduce_k() {
    int i = blockIdx.x * 128 + threadIdx.x;   // 32 x 128 = 4096 rows
    float s = 0.f;
#pragma unroll 8
    for (int p = 0; p < NCOLT; p++)
        s += g_partial[(size_t)p * BN + i];
    float loss = -logf(g_pos[i] / (s + EPSV));
    __shared__ float sh[128];
    sh[threadIdx.x] = loss;
    __syncthreads();
    for (int st = 64; st > 0; st >>= 1) {
        if (threadIdx.x < st) sh[threadIdx.x] += sh[threadIdx.x + st];
        __syncthreads();
    }
    if (threadIdx.x == 0) g_lpart[blockIdx.x] = sh[0];
}

// ---------------------------------------------------------------------------
// Kernel 4: final mean
// ---------------------------------------------------------------------------
__global__ void final_k(float* __restrict__ out) {
    float v = g_lpart[threadIdx.x];
#pragma unroll
    for (int off = 16; off > 0; off >>= 1)
        v += __shfl_down_sync(0xffffffffu, v, off);
    if (threadIdx.x == 0) out[0] = v / (float)BN;
}

// ---------------------------------------------------------------------------
extern "C" void kernel_launch(void* const* d_in, const int* in_sizes, int n_in,
                              void* d_out, int out_size) {
    (void)in_sizes; (void)n_in; (void)out_size;
    const float* f  = (const float*)d_in[0];   // (4096, 1024)
    const float* nz = (const float*)d_in[1];   // (4096, 1024)
    const float* rf = (const float*)d_in[2];   // (4096, 256)
    float* out = (float*)d_out;

    const int DSMEM = 2 * NSTAGE * STAGE_BYTES;   // 147456 B
    cudaFuncSetAttribute(main_k, cudaFuncAttributeMaxDynamicSharedMemorySize, DSMEM);

    prep_k<<<BN, 256>>>((const float4*)f, (const float4*)nz, (const float4*)rf);
    dim3 grid(NCOLT, BN / 128);                // 64 x 32; lower-right-triangle exits early
    main_k<<<grid, 256, DSMEM>>>();
    reduce_k<<<32, 128>>>();
    final_k<<<1, 32>>>(out);
}

// round 17
// speedup vs baseline: 8.6295x; 1.0012x over previous
#include <cuda_runtime.h>
#include <cuda_bf16.h>
#include <math.h>
#include <stdint.h>

#define BN 4096
#define LN 1024
#define DN 256
#define EPSV 1e-6f
#define NCOLT 64      // 64 partial slots (32 left + 32 right)

// per-stage smem tile: 128 rows x 72 bf16 (64 + 8 pad) = 18432 B
#define STAGE_BYTES 18432u
#define NSTAGE 4

// ---------------- device scratch (no allocations allowed) ----------------
__device__ __align__(16) __nv_bfloat16 g_fb[BN * LN];
__device__ __align__(16) __nv_bfloat16 g_nb[BN * LN];
__device__ __align__(16) __nv_bfloat16 g_rb[BN * DN];
__device__ float g_nf[BN], g_nn[BN], g_nr[BN];
__device__ float g_pos[BN];
__device__ float g_partial[NCOLT * BN];
__device__ float g_lpart[32];

// ---------------- PTX helpers (portable sm_80+, no arch suffix) ----------
__device__ __forceinline__ uint32_t su32(const void* p) {
    uint32_t a;
    asm("{ .reg .u64 t; cvta.to.shared.u64 t, %1; cvt.u32.u64 %0, t; }" : "=r"(a) : "l"(p));
    return a;
}
__device__ __forceinline__ void ldsm4(uint32_t* r, uint32_t a) {
    asm volatile("ldmatrix.sync.aligned.m8n8.x4.shared.b16 {%0,%1,%2,%3}, [%4];"
        : "=r"(r[0]), "=r"(r[1]), "=r"(r[2]), "=r"(r[3]) : "r"(a));
}
__device__ __forceinline__ void mma16816(float* c, const uint32_t* a, const uint32_t* b) {
    asm volatile("mma.sync.aligned.m16n8k16.row.col.f32.bf16.bf16.f32 "
        "{%0,%1,%2,%3}, {%4,%5,%6,%7}, {%8,%9}, {%0,%1,%2,%3};"
        : "+f"(c[0]), "+f"(c[1]), "+f"(c[2]), "+f"(c[3])
        : "r"(a[0]), "r"(a[1]), "r"(a[2]), "r"(a[3]), "r"(b[0]), "r"(b[1]));
}
#define CP16(dst, src) \
    asm volatile("cp.async.cg.shared.global [%0], [%1], 16;" :: "r"(dst), "l"(src) : "memory")
#define COMMIT() asm volatile("cp.async.commit_group;" ::: "memory")
#define WAIT2()  asm volatile("cp.async.wait_group 2;" ::: "memory")

// ---------------------------------------------------------------------------
// Kernel 0: fused bf16 convert + fp32 row norms (one read pass). Block = row.
// ---------------------------------------------------------------------------
__global__ void __launch_bounds__(256)
prep_k(const float4* __restrict__ f4,
       const float4* __restrict__ n4,
       const float4* __restrict__ r4) {
    int i = blockIdx.x, t = threadIdx.x;
    int idx = i * 256 + t;                      // float4 index into f / noise
    float4 a = f4[idx];
    float4 b = n4[idx];
    __nv_bfloat162 alo = __floats2bfloat162_rn(a.x, a.y);
    __nv_bfloat162 ahi = __floats2bfloat162_rn(a.z, a.w);
    __nv_bfloat162 blo = __floats2bfloat162_rn(b.x, b.y);
    __nv_bfloat162 bhi = __floats2bfloat162_rn(b.z, b.w);
    uint2 ua, ub;
    ua.x = *(uint32_t*)&alo; ua.y = *(uint32_t*)&ahi;
    ub.x = *(uint32_t*)&blo; ub.y = *(uint32_t*)&bhi;
    ((uint2*)g_fb)[idx] = ua;
    ((uint2*)g_nb)[idx] = ub;
    float sf = a.x * a.x + a.y * a.y + a.z * a.z + a.w * a.w;
    float sn = b.x * b.x + b.y * b.y + b.z * b.z + b.w * b.w;
    float sr = 0.f;
    if (t < 64) {
        int ridx = i * 64 + t;
        float4 c = r4[ridx];
        __nv_bfloat162 clo = __floats2bfloat162_rn(c.x, c.y);
        __nv_bfloat162 chi = __floats2bfloat162_rn(c.z, c.w);
        uint2 uc; uc.x = *(uint32_t*)&clo; uc.y = *(uint32_t*)&chi;
        ((uint2*)g_rb)[ridx] = uc;
        sr = c.x * c.x + c.y * c.y + c.z * c.z + c.w * c.w;
    }
    __shared__ float sh0[256], sh1[256], sh2[256];
    sh0[t] = sf; sh1[t] = sn; sh2[t] = sr;
    __syncthreads();
    for (int s = 128; s > 0; s >>= 1) {
        if (t < s) { sh0[t] += sh0[t + s]; sh1[t] += sh1[t + s]; sh2[t] += sh2[t + s]; }
        __syncthreads();
    }
    if (t == 0) { g_nf[i] = sqrtf(sh0[0]); g_nn[i] = sqrtf(sh1[0]); g_nr[i] = sqrtf(sh2[0]); }
}

// ---------------------------------------------------------------------------
// Kernel 2: bf16 mma.sync dual-GEMM + fused epilogue, 128x128 tiles.
// Right half (f.f^T) is symmetric: only upper-triangle tiles computed; their
// column sums provide the transposed tiles' row sums.
// ---------------------------------------------------------------------------
__global__ void __launch_bounds__(256, 1)
main_k() {
    const int bi = blockIdx.y;            // row block
    const int bx = blockIdx.x;            // 0..31 left (noise), 32..63 right (f)
    const bool right = (bx >= 32);
    const int bj = right ? bx - 32 : bx;  // col block mod 32
    if (right && bi > bj) return;         // lower triangle of right half: skip
    const bool sym = right && (bi < bj);  // off-diagonal: also emit colsums

    extern __shared__ __align__(16) char dyn[];
    __shared__ float s_cn[128], s_cr[128], s_rf[128], s_rr[128];
    __shared__ float srow[128][4];
    __shared__ float scs[128][2];

    const int tid = threadIdx.x;
    const int lane = tid & 31, wid = tid >> 5;
    const int wm = wid >> 2, wn = wid & 3;          // warp grid 2 x 4
    const int rowBase = bi * 128;
    const int colBase = bx * 128;                   // global col (0..8191)
    const int cb2 = bj * 128;                       // col mod B

    const uint32_t aBase = su32(dyn);
    const uint32_t bBase = aBase + NSTAGE * STAGE_BYTES;

    // ldmatrix per-lane base offsets (bytes), padded row stride = 72 el = 144B
    const uint32_t aoff = (uint32_t)(((wm * 64 + (lane & 15)) * 72 + ((lane >> 4) << 3)) * 2);
    const uint32_t boff = (uint32_t)(((wn * 32 + ((lane >> 4) << 3) + (lane & 7)) * 72
                                      + (((lane >> 3) & 1) << 3)) * 2);

    float accF[4][4][4], accR[4][4][4];
#pragma unroll
    for (int a = 0; a < 4; a++)
#pragma unroll
        for (int b = 0; b < 4; b++)
#pragma unroll
            for (int c = 0; c < 4; c++) { accF[a][b][c] = 0.f; accR[a][b][c] = 0.f; }

#define LOADSTEP(Ag, Bg, strideK, s, st) do {                                   \
    uint32_t _ab = aBase + (uint32_t)(st) * STAGE_BYTES;                        \
    uint32_t _bb = bBase + (uint32_t)(st) * STAGE_BYTES;                        \
    _Pragma("unroll")                                                           \
    for (int ii = 0; ii < 4; ii++) {                                            \
        int idx = tid + ii * 256;                                               \
        int r = idx >> 3, c = (idx & 7) * 8;                                    \
        uint32_t so = (uint32_t)((r * 72 + c) * 2);                             \
        CP16(_ab + so, (Ag) + (size_t)r * (strideK) + (s) * 64 + c);            \
        CP16(_bb + so, (Bg) + (size_t)r * (strideK) + (s) * 64 + c);            \
    }                                                                           \
    COMMIT();                                                                   \
} while (0)

#define COMPUTE(st, acc) do {                                                   \
    uint32_t _ab = aBase + (uint32_t)(st) * STAGE_BYTES;                        \
    uint32_t _bb = bBase + (uint32_t)(st) * STAGE_BYTES;                        \
    _Pragma("unroll")                                                           \
    for (int kh = 0; kh < 4; kh++) {                                            \
        uint32_t af[4][4];                                                      \
        _Pragma("unroll")                                                       \
        for (int mt = 0; mt < 4; mt++)                                          \
            ldsm4(af[mt], _ab + aoff + (uint32_t)mt * 2304u + (uint32_t)kh * 32u); \
        uint32_t bf[2][4];                                                      \
        _Pragma("unroll")                                                       \
        for (int p = 0; p < 2; p++)                                             \
            ldsm4(bf[p], _bb + boff + (uint32_t)p * 2304u + (uint32_t)kh * 32u);\
        _Pragma("unroll")                                                       \
        for (int mt = 0; mt < 4; mt++)                                          \
            _Pragma("unroll")                                                   \
            for (int nt = 0; nt < 4; nt++)                                      \
                mma16816(acc[mt][nt], af[mt], &bf[nt >> 1][(nt & 1) * 2]);      \
    }                                                                           \
} while (0)

    // 4-stage pipeline, one __syncthreads per chunk
#define GEMM(Ag, Bg, strideK, NS, acc) do {                                     \
    _Pragma("unroll")                                                           \
    for (int p = 0; p < 3; p++) {                                               \
        if (p < (NS)) LOADSTEP(Ag, Bg, strideK, p, p);                          \
        else COMMIT();                                                          \
    }                                                                           \
    for (int s = 0; s < (NS); s++) {                                            \
        WAIT2();                                                                \
        __syncthreads();                                                        \
        COMPUTE(s & 3, acc);                                                    \
        if (s + 3 < (NS)) LOADSTEP(Ag, Bg, strideK, s + 3, (s + 3) & 3);        \
        else COMMIT();                                                          \
    }                                                                           \
} while (0)

    // GEMM 1: f (rows) x cat (cols), K = 1024, 16 chunks of 64
    {
        const __nv_bfloat16* A1 = g_fb + (size_t)rowBase * LN;
        const __nv_bfloat16* B1 = (right ? g_fb : g_nb) + (size_t)cb2 * LN;
        GEMM(A1, B1, LN, 16, accF);
    }
    // GEMM 2: ref (rows) x ref (cols mod B), K = 256, 4 chunks of 64
    {
        const __nv_bfloat16* A2 = g_rb + (size_t)rowBase * DN;
        const __nv_bfloat16* B2 = g_rb + (size_t)cb2 * DN;
        GEMM(A2, B2, DN, 4, accR);
    }
    asm volatile("cp.async.wait_group 0;" ::: "memory");

    // stage norms
    if (tid < 128) {
        s_rf[tid] = g_nf[rowBase + tid];
        s_rr[tid] = g_nr[rowBase + tid];
        int jm = cb2 + tid;
        s_cn[tid] = right ? g_nf[jm] : g_nn[jm];
        s_cr[tid] = g_nr[jm];
    }
    __syncthreads();

    // ---- fused epilogue ----
    float cs[8];
#pragma unroll
    for (int k = 0; k < 8; k++) cs[k] = 0.f;

#pragma unroll
    for (int mt = 0; mt < 4; mt++) {
#pragma unroll
        for (int h = 0; h < 2; h++) {
            int r = wm * 64 + mt * 16 + h * 8 + (lane >> 2);
            int i = rowBase + r;
            float nfi = s_rf[r], nri = s_rr[r];
            float rs = 0.f;
#pragma unroll
            for (int nt = 0; nt < 4; nt++) {
#pragma unroll
                for (int e = 0; e < 2; e++) {
                    int col = wn * 32 + nt * 8 + (lane & 3) * 2 + e;
                    int j = colBase + col;
                    float v1 = accF[mt][nt][h * 2 + e];
                    float v2 = accR[mt][nt][h * 2 + e];
                    float cf = __fdividef(v1, fmaxf(nfi * s_cn[col], EPSV));
                    float mv = __expf(cf);
                    float w  = 0.5f * (1.0f - __fdividef(v2, fmaxf(nri * s_cr[col], EPSV)));
                    float t = mv * w;
                    if (j == i) { g_pos[i] = mv; t = 0.f; }   // positive pair (left diag)
                    if (j == i + BN) t = 0.f;                 // self pair (right diag)
                    rs += t;
                    cs[nt * 2 + e] += t;                      // colsum (used iff sym)
                }
            }
            rs += __shfl_xor_sync(0xffffffffu, rs, 1);
            rs += __shfl_xor_sync(0xffffffffu, rs, 2);
            if ((lane & 3) == 0) srow[r][wn] = rs;
        }
    }
    if (sym) {
        // reduce colsums over the 8 row-lanes (lane bits 2..4), all rows of wm-half
#pragma unroll
        for (int k = 0; k < 8; k++) {
            cs[k] += __shfl_xor_sync(0xffffffffu, cs[k], 4);
            cs[k] += __shfl_xor_sync(0xffffffffu, cs[k], 8);
            cs[k] += __shfl_xor_sync(0xffffffffu, cs[k], 16);
        }
        if ((lane >> 2) == 0) {
#pragma unroll
            for (int nt = 0; nt < 4; nt++)
#pragma unroll
                for (int e = 0; e < 2; e++) {
                    int col = wn * 32 + nt * 8 + (lane & 3) * 2 + e;
                    scs[col][wm] = cs[nt * 2 + e];
                }
        }
    }
    __syncthreads();
    if (tid < 128) {
        float s = srow[tid][0] + srow[tid][1] + srow[tid][2] + srow[tid][3];
        g_partial[(size_t)bx * BN + rowBase + tid] = s;   // rowsum -> slot bx, block bi
        if (sym) {
            // transposed tile's rowsum = this tile's colsum -> slot 32+bi, block bj
            g_partial[(size_t)(32 + bi) * BN + (size_t)cb2 + tid] = scs[tid][0] + scs[tid][1];
        }
    }
}

// ---------------------------------------------------------------------------
// Kernel 3: per-row negative sum + loss, block partials
// ---------------------------------------------------------------------------
__global__ void reduce_k() {
    int i = blockIdx.x * 128 + threadIdx.x;   // 32 x 128 = 4096 rows
    float s = 0.f;
#pragma unroll 8
    for (int p = 0; p < NCOLT; p++)
        s += g_partial[(size_t)p * BN + i];
    float loss = -logf(g_pos[i] / (s + EPSV));
    __shared__ float sh[128];
    sh[threadIdx.x] = loss;
    __syncthreads();
    for (int st = 64; st > 0; st >>= 1) {
        if (threadIdx.x < st) sh[threadIdx.x] += sh[threadIdx.x + st];
        __syncthreads();
    }
    if (threadIdx.x == 0) g_lpart[blockIdx.x] = sh[0];
}

// ---------------------------------------------------------------------------
// Kernel 4: final mean
// ---------------------------------------------------------------------------
__global__ void final_k(float* __restrict__ out) {
    float v = g_lpart[threadIdx.x];
#pragma unroll
    for (int off = 16; off > 0; off >>= 1)
        v += __shfl_down_sync(0xffffffffu, v, off);
    if (threadIdx.x == 0) out[0] = v / (float)BN;
}

// ---------------------------------------------------------------------------
extern "C" void kernel_launch(void* const* d_in, const int* in_sizes, int n_in,
                              void* d_out, int out_size) {
    (void)in_sizes; (void)n_in; (void)out_size;
    const float* f  = (const float*)d_in[0];   // (4096, 1024)
    const float* nz = (const float*)d_in[1];   // (4096, 1024)
    const float* rf = (const float*)d_in[2];   // (4096, 256)
    float* out = (float*)d_out;

    const int DSMEM = 2 * NSTAGE * STAGE_BYTES;   // 147456 B
    cudaFuncSetAttribute(main_k, cudaFuncAttributeMaxDynamicSharedMemorySize, DSMEM);

    prep_k<<<BN, 256>>>((const float4*)f, (const float4*)nz, (const float4*)rf);
    dim3 grid(NCOLT, BN / 128);                // 64 x 32; lower-right-triangle exits early
    main_k<<<grid, 256, DSMEM>>>();
    reduce_k<<<32, 128>>>();
    final_k<<<1, 32>>>(out);
}